// round 1
// baseline (speedup 1.0000x reference)
#include <cuda_runtime.h>
#include <math.h>

// Problem constants
#define B_ 256
#define R_ 1152
#define C_ 10
#define O_ 16
#define I_ 8
#define RT_ 24              // r's per block
#define RCH_ (R_/RT_)       // 48 r-chunks

// ---------------- device scratch (no allocations allowed) ----------------
__device__ float g_xT[R_*B_*I_];       // x transposed: [r][b][i]   (9.4 MB)
__device__ float g_Wp[R_*C_*I_*O_];    // W reformatted: [r][c][i][o] (5.9 MB)
__device__ float g_b1[R_*C_*B_];       // routing logits b1: [r][c][b] (11.8 MB)
__device__ float g_S[C_*O_*B_];        // numerator accumulator: [c][o][b]
__device__ float g_E[C_*B_];           // softmax denominator:   [c][b]
__device__ float g_v[B_*C_*O_];        // squashed v: [b][c][o]

typedef unsigned long long u64;

// ---------------- packed f32x2 helpers (Blackwell FFMA2) ----------------
__device__ __forceinline__ u64 pk2(float lo, float hi){
    u64 r; asm("mov.b64 %0,{%1,%2};" : "=l"(r) : "f"(lo), "f"(hi)); return r;
}
__device__ __forceinline__ void upk2(u64 v, float& lo, float& hi){
    asm("mov.b64 {%0,%1},%2;" : "=f"(lo), "=f"(hi) : "l"(v));
}
__device__ __forceinline__ u64 ffma2(u64 a, u64 b, u64 c){
    u64 d; asm("fma.rn.f32x2 %0,%1,%2,%3;" : "=l"(d) : "l"(a), "l"(b), "l"(c)); return d;
}
__device__ __forceinline__ u64 fadd2(u64 a, u64 b){
    u64 d; asm("add.rn.f32x2 %0,%1,%2;" : "=l"(d) : "l"(a), "l"(b)); return d;
}

// ---------------- prep kernels ----------------
// xT[r][b][i] = x[b][r][i]
__global__ void prep_x(const float* __restrict__ x){
    int t = blockIdx.x*256 + threadIdx.x;            // over R_*B_
    int r = t / B_, b = t % B_;
    const float4* src = reinterpret_cast<const float4*>(x + (b*R_ + r)*I_);
    float4* dst = reinterpret_cast<float4*>(g_xT + t*I_);
    dst[0] = src[0];
    dst[1] = src[1];
}

// Wp[r][c][i][o] = W[r][c][o][i]  (o contiguous -> natural f32x2 o-pairs)
__global__ void prep_W(const float* __restrict__ W){
    int t = blockIdx.x*256 + threadIdx.x;            // over R_*C_*O_
    int o = t % O_; int rc = t / O_;
    const float* src = W + t*I_;                     // W[rc][o][0..7]
    float* dst = g_Wp + rc*(I_*O_);
#pragma unroll
    for (int i = 0; i < I_; i++) dst[i*O_ + o] = src[i];
}

__global__ void zero_SE(){
    int t = blockIdx.x*256 + threadIdx.x;            // 40960 threads = |g_S|
    g_S[t] = 0.f;
    if (t < C_*B_) g_E[t] = 0.f;
}

// ---------------- fused routing pass ----------------
// MODE 0: S += u_hat                        (uniform coupling, iteration 0)
// MODE 1: b1 = u.v0 (store), S += e*u, E += e,  e = exp(b1)
// MODE 2: b2 = b1 + u.v1,    S += e*u, E += e,  e = exp(b2)
// Block = (c, r-chunk); lane = b.
template<int MODE>
__global__ void __launch_bounds__(256) pass_kernel(){
    __shared__ __align__(16) float Ws[RT_*I_*O_];    // 12 KB W slice for this c
    const int c  = blockIdx.y;
    const int r0 = blockIdx.x * RT_;
    const int b  = threadIdx.x;

    // cooperative W stage: RT_*32 float4 rows
    for (int idx = threadIdx.x; idx < RT_*32; idx += 256){
        int rl = idx >> 5, w = idx & 31;
        reinterpret_cast<float4*>(Ws)[idx] =
            reinterpret_cast<const float4*>(g_Wp)[((r0+rl)*C_ + c)*32 + w];
    }
    __syncthreads();

    u64 v2[8];
    if (MODE){
        const float4* vp = reinterpret_cast<const float4*>(g_v + (b*C_ + c)*O_);
#pragma unroll
        for (int q = 0; q < 4; q++){
            float4 f = vp[q];
            v2[2*q]   = pk2(f.x, f.y);
            v2[2*q+1] = pk2(f.z, f.w);
        }
    }

    u64 accS[8];
#pragma unroll
    for (int j = 0; j < 8; j++) accS[j] = 0ull;
    float accE = 0.f;

#pragma unroll 1
    for (int rl = 0; rl < RT_; rl++){
        const int r = r0 + rl;
        const float4* xp = reinterpret_cast<const float4*>(g_xT + (r*B_ + b)*I_);
        float4 xa = xp[0], xb = xp[1];
        float xs[8] = {xa.x, xa.y, xa.z, xa.w, xb.x, xb.y, xb.z, xb.w};

        u64 u2[8];
#pragma unroll
        for (int j = 0; j < 8; j++) u2[j] = 0ull;

        const float* wrow = Ws + rl*(I_*O_);
#pragma unroll
        for (int i = 0; i < I_; i++){
            u64 xd = pk2(xs[i], xs[i]);
            const ulonglong2* wp = reinterpret_cast<const ulonglong2*>(wrow + i*O_);
#pragma unroll
            for (int jj = 0; jj < 4; jj++){
                ulonglong2 ww = wp[jj];                 // LDS.128 broadcast
                u2[2*jj]   = ffma2(ww.x, xd, u2[2*jj]);
                u2[2*jj+1] = ffma2(ww.y, xd, u2[2*jj+1]);
            }
        }

        if (MODE == 0){
#pragma unroll
            for (int j = 0; j < 8; j++) accS[j] = fadd2(accS[j], u2[j]);
        } else {
            // t = <u, v>  (two chains to shorten dependency)
            u64 ta = 0ull, tb = 0ull;
#pragma unroll
            for (int j = 0; j < 4; j++){
                ta = ffma2(u2[2*j],   v2[2*j],   ta);
                tb = ffma2(u2[2*j+1], v2[2*j+1], tb);
            }
            u64 t2 = fadd2(ta, tb);
            float tl, th; upk2(t2, tl, th);
            float t = tl + th;

            const int bidx = (r*C_ + c)*B_ + b;
            if (MODE == 2) t += g_b1[bidx];
            else           g_b1[bidx] = t;

            float e = __expf(t);
            accE += e;
            u64 ed = pk2(e, e);
#pragma unroll
            for (int j = 0; j < 8; j++) accS[j] = ffma2(u2[j], ed, accS[j]);
        }
    }

    // one coalesced flush per block
#pragma unroll
    for (int j = 0; j < 8; j++){
        float lo, hi; upk2(accS[j], lo, hi);
        atomicAdd(&g_S[(c*O_ + 2*j    )*B_ + b], lo);
        atomicAdd(&g_S[(c*O_ + 2*j + 1)*B_ + b], hi);
    }
    if (MODE) atomicAdd(&g_E[c*B_ + b], accE);
}

// ---------------- squash (+ normalization + accumulator re-zero) ----------------
// mode 0: s = S / R   (uniform coupling); mode 1: s = S / E (softmax-normalized)
__global__ void squash_kernel(float* out, int mode){
    int idx = blockIdx.x*256 + threadIdx.x;          // 40960 = B*C*O
    int o  = idx & 15;
    int g  = idx >> 4;                               // g = b*C + c
    int cc = g % C_, bb = g / C_;
    int sidx = (cc*O_ + o)*B_ + bb;

    float s = g_S[sidx];
    if (mode == 0) s *= (1.0f / R_);
    else           s /= g_E[cc*B_ + bb];

    float sq = s*s;
#pragma unroll
    for (int off = 8; off >= 1; off >>= 1)
        sq += __shfl_xor_sync(0xffffffffu, sq, off, 16);

    float scale = sq / ((1.0f + sq) * sqrtf(sq + 1e-7f));
    float* dst = out ? out : g_v;
    dst[g*O_ + o] = scale * s;

    // re-zero accumulators for the next pass / next graph replay
    g_S[sidx] = 0.f;
    if (o == 0) g_E[cc*B_ + bb] = 0.f;
}

// ---------------- launch ----------------
extern "C" void kernel_launch(void* const* d_in, const int* in_sizes, int n_in,
                              void* d_out, int out_size){
    const float* x = (const float*)d_in[0];
    const float* W = (const float*)d_in[1];
    // defensive: identify by size (x has 2359296 elems, W has 1474560)
    if (n_in >= 2 && in_sizes[0] == R_*C_*O_*I_){ const float* t = x; x = W; W = t; }

    prep_x<<<(R_*B_)/256, 256>>>(x);
    prep_W<<<(R_*C_*O_)/256, 256>>>(W);
    zero_SE<<<160, 256>>>();

    dim3 grid(RCH_, C_);
    pass_kernel<0><<<grid, 256>>>();
    squash_kernel<<<160, 256>>>(nullptr, 0);         // v0
    pass_kernel<1><<<grid, 256>>>();
    squash_kernel<<<160, 256>>>(nullptr, 1);         // v1
    pass_kernel<2><<<grid, 256>>>();
    squash_kernel<<<160, 256>>>((float*)d_out, 1);   // v2 -> output (B,1,C,O,1)
}

// round 2
// speedup vs baseline: 1.0002x; 1.0002x over previous
#include <cuda_runtime.h>
#include <math.h>

// Problem constants
#define B_ 256
#define R_ 1152
#define C_ 10
#define O_ 16
#define I_ 8
#define RT_ 24              // r's per block
#define RCH_ (R_/RT_)       // 48 r-chunks

// ---------------- device scratch (no allocations allowed) ----------------
__device__ float g_xT[R_*B_*I_];       // x transposed: [r][b][i]   (9.4 MB)
__device__ float g_Wp[R_*C_*I_*O_];    // W reformatted: [r][c][i][o] (5.9 MB)
__device__ float g_b1[R_*C_*B_];       // routing logits b1: [r][c][b] (11.8 MB)
__device__ float g_S[C_*O_*B_];        // numerator accumulator: [c][o][b]
__device__ float g_E[C_*B_];           // softmax denominator:   [c][b]
__device__ float g_v[B_*C_*O_];        // squashed v: [b][c][o]

typedef unsigned long long u64;

// ---------------- packed f32x2 helpers (Blackwell FFMA2) ----------------
__device__ __forceinline__ u64 pk2(float lo, float hi){
    u64 r; asm("mov.b64 %0,{%1,%2};" : "=l"(r) : "f"(lo), "f"(hi)); return r;
}
__device__ __forceinline__ void upk2(u64 v, float& lo, float& hi){
    asm("mov.b64 {%0,%1},%2;" : "=f"(lo), "=f"(hi) : "l"(v));
}
__device__ __forceinline__ u64 ffma2(u64 a, u64 b, u64 c){
    u64 d; asm("fma.rn.f32x2 %0,%1,%2,%3;" : "=l"(d) : "l"(a), "l"(b), "l"(c)); return d;
}
__device__ __forceinline__ u64 fadd2(u64 a, u64 b){
    u64 d; asm("add.rn.f32x2 %0,%1,%2;" : "=l"(d) : "l"(a), "l"(b)); return d;
}

// ---------------- prep kernels ----------------
// xT[r][b][i] = x[b][r][i]
__global__ void prep_x(const float* __restrict__ x){
    int t = blockIdx.x*256 + threadIdx.x;            // over R_*B_
    int r = t / B_, b = t % B_;
    const float4* src = reinterpret_cast<const float4*>(x + (b*R_ + r)*I_);
    float4* dst = reinterpret_cast<float4*>(g_xT + t*I_);
    dst[0] = src[0];
    dst[1] = src[1];
}

// Wp[r][c][i][o] = W[r][c][o][i]  (o contiguous -> natural f32x2 o-pairs)
__global__ void prep_W(const float* __restrict__ W){
    int t = blockIdx.x*256 + threadIdx.x;            // over R_*C_*O_
    int o = t % O_; int rc = t / O_;
    const float* src = W + t*I_;                     // W[rc][o][0..7]
    float* dst = g_Wp + rc*(I_*O_);
#pragma unroll
    for (int i = 0; i < I_; i++) dst[i*O_ + o] = src[i];
}

__global__ void zero_SE(){
    int t = blockIdx.x*256 + threadIdx.x;            // 40960 threads = |g_S|
    g_S[t] = 0.f;
    if (t < C_*B_) g_E[t] = 0.f;
}

// ---------------- fused routing pass ----------------
// MODE 0: S += u_hat                        (uniform coupling, iteration 0)
// MODE 1: b1 = u.v0 (store), S += e*u, E += e,  e = exp(b1)
// MODE 2: b2 = b1 + u.v1,    S += e*u, E += e,  e = exp(b2)
// Block = (c, r-chunk); lane = b.
template<int MODE>
__global__ void __launch_bounds__(256) pass_kernel(){
    __shared__ __align__(16) float Ws[RT_*I_*O_];    // 12 KB W slice for this c
    const int c  = blockIdx.y;
    const int r0 = blockIdx.x * RT_;
    const int b  = threadIdx.x;

    // cooperative W stage: RT_*32 float4 rows
    for (int idx = threadIdx.x; idx < RT_*32; idx += 256){
        int rl = idx >> 5, w = idx & 31;
        reinterpret_cast<float4*>(Ws)[idx] =
            reinterpret_cast<const float4*>(g_Wp)[((r0+rl)*C_ + c)*32 + w];
    }
    __syncthreads();

    u64 v2[8];
    if (MODE){
        const float4* vp = reinterpret_cast<const float4*>(g_v + (b*C_ + c)*O_);
#pragma unroll
        for (int q = 0; q < 4; q++){
            float4 f = vp[q];
            v2[2*q]   = pk2(f.x, f.y);
            v2[2*q+1] = pk2(f.z, f.w);
        }
    }

    u64 accS[8];
#pragma unroll
    for (int j = 0; j < 8; j++) accS[j] = 0ull;
    float accE = 0.f;

#pragma unroll 1
    for (int rl = 0; rl < RT_; rl++){
        const int r = r0 + rl;
        const float4* xp = reinterpret_cast<const float4*>(g_xT + (r*B_ + b)*I_);
        float4 xa = xp[0], xb = xp[1];
        float xs[8] = {xa.x, xa.y, xa.z, xa.w, xb.x, xb.y, xb.z, xb.w};

        u64 u2[8];
#pragma unroll
        for (int j = 0; j < 8; j++) u2[j] = 0ull;

        const float* wrow = Ws + rl*(I_*O_);
#pragma unroll
        for (int i = 0; i < I_; i++){
            u64 xd = pk2(xs[i], xs[i]);
            const ulonglong2* wp = reinterpret_cast<const ulonglong2*>(wrow + i*O_);
#pragma unroll
            for (int jj = 0; jj < 4; jj++){
                ulonglong2 ww = wp[jj];                 // LDS.128 broadcast
                u2[2*jj]   = ffma2(ww.x, xd, u2[2*jj]);
                u2[2*jj+1] = ffma2(ww.y, xd, u2[2*jj+1]);
            }
        }

        if (MODE == 0){
#pragma unroll
            for (int j = 0; j < 8; j++) accS[j] = fadd2(accS[j], u2[j]);
        } else {
            // t = <u, v>  (two chains to shorten dependency)
            u64 ta = 0ull, tb = 0ull;
#pragma unroll
            for (int j = 0; j < 4; j++){
                ta = ffma2(u2[2*j],   v2[2*j],   ta);
                tb = ffma2(u2[2*j+1], v2[2*j+1], tb);
            }
            u64 t2 = fadd2(ta, tb);
            float tl, th; upk2(t2, tl, th);
            float t = tl + th;

            const int bidx = (r*C_ + c)*B_ + b;
            if (MODE == 2) t += g_b1[bidx];
            else           g_b1[bidx] = t;

            float e = __expf(t);
            accE += e;
            u64 ed = pk2(e, e);
#pragma unroll
            for (int j = 0; j < 8; j++) accS[j] = ffma2(u2[j], ed, accS[j]);
        }
    }

    // one coalesced flush per block
#pragma unroll
    for (int j = 0; j < 8; j++){
        float lo, hi; upk2(accS[j], lo, hi);
        atomicAdd(&g_S[(c*O_ + 2*j    )*B_ + b], lo);
        atomicAdd(&g_S[(c*O_ + 2*j + 1)*B_ + b], hi);
    }
    if (MODE) atomicAdd(&g_E[c*B_ + b], accE);
}

// ---------------- squash (+ normalization + accumulator re-zero) ----------------
// mode 0: s = S / R   (uniform coupling); mode 1: s = S / E (softmax-normalized)
__global__ void squash_kernel(float* out, int mode){
    int idx = blockIdx.x*256 + threadIdx.x;          // 40960 = B*C*O
    int o  = idx & 15;
    int g  = idx >> 4;                               // g = b*C + c
    int cc = g % C_, bb = g / C_;
    int sidx = (cc*O_ + o)*B_ + bb;

    float s = g_S[sidx];
    if (mode == 0) s *= (1.0f / R_);
    else           s /= g_E[cc*B_ + bb];

    float sq = s*s;
#pragma unroll
    for (int off = 8; off >= 1; off >>= 1)
        sq += __shfl_xor_sync(0xffffffffu, sq, off, 16);

    float scale = sq / ((1.0f + sq) * sqrtf(sq + 1e-7f));
    float* dst = out ? out : g_v;
    dst[g*O_ + o] = scale * s;

    // re-zero accumulators for the next pass / next graph replay
    g_S[sidx] = 0.f;
    if (o == 0) g_E[cc*B_ + bb] = 0.f;
}

// ---------------- launch ----------------
extern "C" void kernel_launch(void* const* d_in, const int* in_sizes, int n_in,
                              void* d_out, int out_size){
    const float* x = (const float*)d_in[0];
    const float* W = (const float*)d_in[1];
    // defensive: identify by size (x has 2359296 elems, W has 1474560)
    if (n_in >= 2 && in_sizes[0] == R_*C_*O_*I_){ const float* t = x; x = W; W = t; }

    prep_x<<<(R_*B_)/256, 256>>>(x);
    prep_W<<<(R_*C_*O_)/256, 256>>>(W);
    zero_SE<<<160, 256>>>();

    dim3 grid(RCH_, C_);
    pass_kernel<0><<<grid, 256>>>();
    squash_kernel<<<160, 256>>>(nullptr, 0);         // v0
    pass_kernel<1><<<grid, 256>>>();
    squash_kernel<<<160, 256>>>(nullptr, 1);         // v1
    pass_kernel<2><<<grid, 256>>>();
    squash_kernel<<<160, 256>>>((float*)d_out, 1);   // v2 -> output (B,1,C,O,1)
}

// round 4
// speedup vs baseline: 1.3808x; 1.3805x over previous
#include <cuda_runtime.h>
#include <math.h>

// Problem constants
#define B_ 256
#define R_ 1152
#define C_ 10
#define O_ 16
#define I_ 8
#define RT_ 12              // r's per block
#define RCH_ (R_/RT_)       // 96 r-chunks

// ---------------- device scratch (no allocations allowed) ----------------
__device__ float g_xT[R_*B_*I_];       // x transposed: [r][b][i]   (9.4 MB)
__device__ float g_Wp[R_*C_*I_*O_];    // W reformatted: [r][c][i][o] (5.9 MB)
__device__ float g_b1[R_*C_*B_];       // routing logits b1: [r][c][b] (11.8 MB)
__device__ float g_S[C_*O_*B_];        // numerator accumulator: [c][o][b]
__device__ float g_E[C_*B_];           // softmax denominator:   [c][b]
__device__ float g_v[B_*C_*O_];        // squashed v: [b][c][o]

typedef unsigned long long u64;

// ---------------- packed f32x2 helpers (Blackwell FFMA2) ----------------
__device__ __forceinline__ u64 pk2(float lo, float hi){
    u64 r; asm("mov.b64 %0,{%1,%2};" : "=l"(r) : "f"(lo), "f"(hi)); return r;
}
__device__ __forceinline__ void upk2(u64 v, float& lo, float& hi){
    asm("mov.b64 {%0,%1},%2;" : "=f"(lo), "=f"(hi) : "l"(v));
}
__device__ __forceinline__ u64 ffma2(u64 a, u64 b, u64 c){
    u64 d; asm("fma.rn.f32x2 %0,%1,%2,%3;" : "=l"(d) : "l"(a), "l"(b), "l"(c)); return d;
}
__device__ __forceinline__ u64 fadd2(u64 a, u64 b){
    u64 d; asm("add.rn.f32x2 %0,%1,%2;" : "=l"(d) : "l"(a), "l"(b)); return d;
}

// ---------------- prep kernels ----------------
// xT[r][b][i] = x[b][r][i]
__global__ void prep_x(const float* __restrict__ x){
    int t = blockIdx.x*256 + threadIdx.x;            // over R_*B_
    int r = t / B_, b = t % B_;
    const float4* src = reinterpret_cast<const float4*>(x + (b*R_ + r)*I_);
    float4* dst = reinterpret_cast<float4*>(g_xT + t*I_);
    dst[0] = src[0];
    dst[1] = src[1];
}

// Wp[r][c][i][o] = W[r][c][o][i]  (o contiguous -> natural f32x2 o-pairs)
// also zeroes g_S / g_E (fused to save a launch)
__global__ void prep_W(const float* __restrict__ W){
    int t = blockIdx.x*256 + threadIdx.x;            // over R_*C_*O_ = 184320
    int o = t % O_; int rc = t / O_;
    const float* src = W + t*I_;                     // W[rc][o][0..7]
    float* dst = g_Wp + rc*(I_*O_);
#pragma unroll
    for (int i = 0; i < I_; i++) dst[i*O_ + o] = src[i];

    if (t < C_*O_*B_) g_S[t] = 0.f;
    if (t < C_*B_)    g_E[t] = 0.f;
}

// ---------------- fused routing pass ----------------
// MODE 0: S += u_hat                        (uniform coupling, iteration 0)
// MODE 1: b1 = u.v0 (store), S += e*u, E += e,  e = exp(b1)
// MODE 2: b2 = b1 + u.v1,    S += e*u, E += e,  e = exp(b2)
// Block = (c, r-chunk of 12); 128 threads, each handles b = tid and b = tid+128.
template<int MODE>
__global__ void __launch_bounds__(128, 3) pass_kernel(){
    __shared__ __align__(16) float Ws[RT_*I_*O_];    // 6 KB W slice for this c
    const int c   = blockIdx.y;
    const int r0  = blockIdx.x * RT_;
    const int tid = threadIdx.x;
    const int b0  = tid;
    const int b1  = tid + 128;

    // cooperative W stage: RT_*32 float4 rows, 3 per thread
    for (int idx = tid; idx < RT_*32; idx += 128){
        int rl = idx >> 5, w = idx & 31;
        reinterpret_cast<float4*>(Ws)[idx] =
            reinterpret_cast<const float4*>(g_Wp)[((r0+rl)*C_ + c)*32 + w];
    }
    __syncthreads();

    u64 va[8], vb[8];
    if (MODE){
        const float4* vpa = reinterpret_cast<const float4*>(g_v + (b0*C_ + c)*O_);
        const float4* vpb = reinterpret_cast<const float4*>(g_v + (b1*C_ + c)*O_);
#pragma unroll
        for (int q = 0; q < 4; q++){
            float4 f = vpa[q]; va[2*q] = pk2(f.x, f.y); va[2*q+1] = pk2(f.z, f.w);
            float4 g = vpb[q]; vb[2*q] = pk2(g.x, g.y); vb[2*q+1] = pk2(g.z, g.w);
        }
    }

    u64 Sa[8], Sb[8];
#pragma unroll
    for (int j = 0; j < 8; j++){ Sa[j] = 0ull; Sb[j] = 0ull; }
    float Ea = 0.f, Eb = 0.f;

    // prefetch x for rl = 0 (both b's)
    float4 nxa0, nxa1, nxb0, nxb1;
    {
        const float4* pa = reinterpret_cast<const float4*>(g_xT + (r0*B_ + b0)*I_);
        const float4* pb = reinterpret_cast<const float4*>(g_xT + (r0*B_ + b1)*I_);
        nxa0 = pa[0]; nxa1 = pa[1]; nxb0 = pb[0]; nxb1 = pb[1];
    }

#pragma unroll 1
    for (int rl = 0; rl < RT_; rl++){
        const float xsa[8] = {nxa0.x, nxa0.y, nxa0.z, nxa0.w, nxa1.x, nxa1.y, nxa1.z, nxa1.w};
        const float xsb[8] = {nxb0.x, nxb0.y, nxb0.z, nxb0.w, nxb1.x, nxb1.y, nxb1.z, nxb1.w};

        // prefetch next rl's x (latency hidden behind this rl's compute)
        if (rl + 1 < RT_){
            const float4* pa = reinterpret_cast<const float4*>(g_xT + ((r0+rl+1)*B_ + b0)*I_);
            const float4* pb = reinterpret_cast<const float4*>(g_xT + ((r0+rl+1)*B_ + b1)*I_);
            nxa0 = pa[0]; nxa1 = pa[1]; nxb0 = pb[0]; nxb1 = pb[1];
        }

        u64 ua[8], ub[8];
#pragma unroll
        for (int j = 0; j < 8; j++){ ua[j] = 0ull; ub[j] = 0ull; }

        const float* wrow = Ws + rl*(I_*O_);
#pragma unroll
        for (int i = 0; i < I_; i++){
            u64 xda = pk2(xsa[i], xsa[i]);
            u64 xdb = pk2(xsb[i], xsb[i]);
            const ulonglong2* wp = reinterpret_cast<const ulonglong2*>(wrow + i*O_);
#pragma unroll
            for (int jj = 0; jj < 4; jj++){
                ulonglong2 ww = wp[jj];                 // LDS.128 broadcast, shared by both b's
                ua[2*jj]   = ffma2(ww.x, xda, ua[2*jj]);
                ua[2*jj+1] = ffma2(ww.y, xda, ua[2*jj+1]);
                ub[2*jj]   = ffma2(ww.x, xdb, ub[2*jj]);
                ub[2*jj+1] = ffma2(ww.y, xdb, ub[2*jj+1]);
            }
        }

        if (MODE == 0){
#pragma unroll
            for (int j = 0; j < 8; j++){
                Sa[j] = fadd2(Sa[j], ua[j]);
                Sb[j] = fadd2(Sb[j], ub[j]);
            }
        } else {
            // t = <u, v>  (4 independent chains)
            u64 t0 = 0ull, t1 = 0ull, t2 = 0ull, t3 = 0ull;
#pragma unroll
            for (int j = 0; j < 4; j++){
                t0 = ffma2(ua[2*j],   va[2*j],   t0);
                t1 = ffma2(ua[2*j+1], va[2*j+1], t1);
                t2 = ffma2(ub[2*j],   vb[2*j],   t2);
                t3 = ffma2(ub[2*j+1], vb[2*j+1], t3);
            }
            float l, h, ta, tb_;
            upk2(fadd2(t0, t1), l, h); ta  = l + h;
            upk2(fadd2(t2, t3), l, h); tb_ = l + h;

            const int r = r0 + rl;
            const int bidx = (r*C_ + c)*B_ + b0;
            if (MODE == 2){ ta += g_b1[bidx]; tb_ += g_b1[bidx + 128]; }
            else          { g_b1[bidx] = ta;  g_b1[bidx + 128] = tb_;  }

            float ea = __expf(ta), eb = __expf(tb_);
            Ea += ea; Eb += eb;
            u64 eda = pk2(ea, ea), edb = pk2(eb, eb);
#pragma unroll
            for (int j = 0; j < 8; j++){
                Sa[j] = ffma2(ua[j], eda, Sa[j]);
                Sb[j] = ffma2(ub[j], edb, Sb[j]);
            }
        }
    }

    // one coalesced flush per block (distinct addresses per lane)
#pragma unroll
    for (int j = 0; j < 8; j++){
        float lo, hi;
        upk2(Sa[j], lo, hi);
        atomicAdd(&g_S[(c*O_ + 2*j    )*B_ + b0], lo);
        atomicAdd(&g_S[(c*O_ + 2*j + 1)*B_ + b0], hi);
        upk2(Sb[j], lo, hi);
        atomicAdd(&g_S[(c*O_ + 2*j    )*B_ + b1], lo);
        atomicAdd(&g_S[(c*O_ + 2*j + 1)*B_ + b1], hi);
    }
    if (MODE){
        atomicAdd(&g_E[c*B_ + b0], Ea);
        atomicAdd(&g_E[c*B_ + b1], Eb);
    }
}

// ---------------- squash (+ normalization + accumulator re-zero) ----------------
// mode 0: s = S / R   (uniform coupling); mode 1: s = S / E (softmax-normalized)
__global__ void squash_kernel(float* out, int mode){
    int idx = blockIdx.x*256 + threadIdx.x;          // 40960 = B*C*O
    int o  = idx & 15;
    int g  = idx >> 4;                               // g = b*C + c
    int cc = g % C_, bb = g / C_;
    int sidx = (cc*O_ + o)*B_ + bb;

    float s = g_S[sidx];
    if (mode == 0) s *= (1.0f / R_);
    else           s /= g_E[cc*B_ + bb];

    float sq = s*s;
#pragma unroll
    for (int off = 8; off >= 1; off >>= 1)
        sq += __shfl_xor_sync(0xffffffffu, sq, off, 16);

    float scale = sq / ((1.0f + sq) * sqrtf(sq + 1e-7f));
    float* dst = out ? out : g_v;
    dst[g*O_ + o] = scale * s;

    // re-zero accumulators for the next pass / next graph replay
    g_S[sidx] = 0.f;
    if (o == 0) g_E[cc*B_ + bb] = 0.f;
}

// ---------------- launch ----------------
extern "C" void kernel_launch(void* const* d_in, const int* in_sizes, int n_in,
                              void* d_out, int out_size){
    const float* x = (const float*)d_in[0];
    const float* W = (const float*)d_in[1];
    // defensive: identify by size (x has 2359296 elems, W has 1474560)
    if (n_in >= 2 && in_sizes[0] == R_*C_*O_*I_){ const float* t = x; x = W; W = t; }

    prep_x<<<(R_*B_)/256, 256>>>(x);
    prep_W<<<(R_*C_*O_)/256, 256>>>(W);   // also zeroes g_S/g_E

    dim3 grid(RCH_, C_);
    pass_kernel<0><<<grid, 128>>>();
    squash_kernel<<<160, 256>>>(nullptr, 0);         // v0
    pass_kernel<1><<<grid, 128>>>();
    squash_kernel<<<160, 256>>>(nullptr, 1);         // v1
    pass_kernel<2><<<grid, 128>>>();
    squash_kernel<<<160, 256>>>((float*)d_out, 1);   // v2 -> output (B,1,C,O,1)
}